// round 2
// baseline (speedup 1.0000x reference)
#include <cuda_runtime.h>
#include <cuda_bf16.h>
#include <cstdint>

#define Tt   4096
#define Hh   512
#define H3   1536
#define WNw  4
#define NCTA 128
#define NTH  256
#define Sdim 4

__device__ float g_XW  [Tt * H3];
__device__ float g_XWa [Tt * Hh];
__device__ float g_XwWw[Tt * WNw * H3];
__device__ float g_HUw [Tt * H3];
__device__ float g_cw  [WNw * Hh];
__device__ unsigned g_bar;
__device__ int g_mask_kind;

// ---- mask dtype detection (u8/i32/f32) + barrier reset ----
__global__ void detect_and_reset(const unsigned* __restrict__ wm) {
    __shared__ int f_gt1, f_f32;
    if (threadIdx.x == 0) { f_gt1 = 0; f_f32 = 0; }
    __syncthreads();
    for (int i = threadIdx.x; i < 4096; i += blockDim.x) {
        unsigned v = wm[i];
        if (v == 0x3F800000u) atomicOr(&f_f32, 1);
        else if (v > 1u)      atomicOr(&f_gt1, 1);
    }
    __syncthreads();
    if (threadIdx.x == 0) {
        g_mask_kind = f_f32 ? 2 : (f_gt1 ? 0 : 1);
        g_bar = 0u;
    }
}

// ---- batched GEMM with optional row-gather: C = gather(A)@B + bias ----
#define BM 64
#define BN 64
#define BK 8
__global__ void gemm_bias_kernel(const float* __restrict__ A, const int* __restrict__ idx,
                                 const float* __restrict__ B, const float* __restrict__ bias,
                                 float* __restrict__ C, int M, int K, int N) {
    __shared__ float As[BK][BM];
    __shared__ float Bs[BK][BN];
    const int bm0 = blockIdx.y * BM, bn0 = blockIdx.x * BN;
    const int tid = threadIdx.x;
    const int tx = tid & 15, ty = tid >> 4;
    const int lm = tid >> 2, lkk = (tid & 3) * 2;
    int arow = bm0 + lm;
    if (idx) arow = idx[arow];
    const float* aptr = A + (size_t)arow * K;
    const int bn = tid & 63, bkk = tid >> 6;

    float acc[4][4];
#pragma unroll
    for (int i = 0; i < 4; ++i)
#pragma unroll
        for (int j = 0; j < 4; ++j) acc[i][j] = 0.f;

    for (int k0 = 0; k0 < K; k0 += BK) {
        As[lkk][lm]     = aptr[k0 + lkk];
        As[lkk + 1][lm] = aptr[k0 + lkk + 1];
        Bs[bkk][bn]     = B[(size_t)(k0 + bkk) * N + bn0 + bn];
        Bs[bkk + 4][bn] = B[(size_t)(k0 + bkk + 4) * N + bn0 + bn];
        __syncthreads();
#pragma unroll
        for (int kk = 0; kk < BK; ++kk) {
            float4 av = *reinterpret_cast<const float4*>(&As[kk][ty * 4]);
            float4 bv = *reinterpret_cast<const float4*>(&Bs[kk][tx * 4]);
            float a[4] = {av.x, av.y, av.z, av.w};
            float b4[4] = {bv.x, bv.y, bv.z, bv.w};
#pragma unroll
            for (int i = 0; i < 4; ++i)
#pragma unroll
                for (int j = 0; j < 4; ++j) acc[i][j] += a[i] * b4[j];
        }
        __syncthreads();
    }
#pragma unroll
    for (int i = 0; i < 4; ++i) {
        size_t rbase = (size_t)(bm0 + ty * 4 + i) * N + bn0 + tx * 4;
#pragma unroll
        for (int j = 0; j < 4; ++j)
            C[rbase + j] = acc[i][j] + bias[bn0 + tx * 4 + j];
    }
}

// ---- grid-wide barrier (all 128 CTAs co-resident) ----
__device__ __forceinline__ void gbar(unsigned target) {
    __threadfence();
    __syncthreads();
    if (threadIdx.x == 0) {
        asm volatile("red.release.gpu.add.u32 [%0], %1;" :: "l"(&g_bar), "r"(1u) : "memory");
        unsigned v;
        for (;;) {
            asm volatile("ld.acquire.gpu.u32 %0, [%1];" : "=r"(v) : "l"(&g_bar) : "memory");
            if (v >= target) break;
            __nanosleep(32);
        }
    }
    __syncthreads();
}

#define SMEM_FLOATS 17020
#define SMEM_BYTES  (SMEM_FLOATS * 4)

__global__ void lattice_seq_kernel(const float* __restrict__ h0, const float* __restrict__ c0,
                                   const int* __restrict__ wstarts, const void* __restrict__ wmask,
                                   const float* __restrict__ U, const float* __restrict__ Ua,
                                   const float* __restrict__ Uw, float* __restrict__ out) {
    extern __shared__ float sm[];
    float* sU     = sm;            // [12*512] U cols (g*512 + r*4 + jl)
    float* sUw    = sm + 6144;     // [12*512] Uw cols
    float* sUa    = sm + 12288;    // [4*512]  Ua cols
    float* sh     = sm + 14336;    // [512]    h_prev
    float* scw    = sm + 14848;    // [4*512]  full c_w
    float* sg     = sm + 16896;    // [12] gates (i|o|g per jl)
    float* shuw   = sm + 16912;    // [12] h_{t-1}@Uw own cols
    float* salpha = sm + 16928;    // [16]
    float* sxw    = sm + 16944;    // [12]
    float* sxa    = sm + 16960;    // [4]
    float* sxww   = sm + 16964;    // [48]
    int*   smask  = (int*)(sm + 17012);
    int*   sstart = (int*)(sm + 17016);

    const int tid = threadIdx.x;
    const int r   = blockIdx.x;
    const int grp = tid >> 3, lane = tid & 7;

    for (int e = tid; e < 12 * 512; e += NTH) {
        int d = e >> 9, i = e & 511;
        int col = (d >> 2) * 512 + r * Sdim + (d & 3);
        sU[e]  = U[(size_t)i * H3 + col];
        sUw[e] = Uw[(size_t)i * H3 + col];
    }
    for (int e = tid; e < 4 * 512; e += NTH) {
        int jl = e >> 9, i = e & 511;
        sUa[e] = Ua[(size_t)i * Hh + r * Sdim + jl];
    }
    const int mk = g_mask_kind;

    for (int t = 0; t < Tt; ++t) {
        // prefetch step constants (recurrence-independent)
        if (tid < 4) {
            int w = tid, q = t * 4 + w;
            int m;
            if (mk == 0)      m = ((const unsigned char*)wmask)[q] != 0;
            else if (mk == 2) m = ((const float*)wmask)[q] != 0.f;
            else              m = ((const int*)wmask)[q] != 0;
            smask[w]  = m;
            sstart[w] = wstarts[q];
            sxa[w]    = g_XWa[(size_t)t * Hh + r * Sdim + w];
        } else if (tid >= 32 && tid < 44) {
            int d = tid - 32;
            int col = (d >> 2) * 512 + r * Sdim + (d & 3);
            sxw[d] = g_XW[(size_t)t * H3 + col];
        } else if (tid >= 64 && tid < 112) {
            int e = tid - 64, w = e / 12, d = e % 12;
            int col = (d >> 2) * 512 + r * Sdim + (d & 3);
            sxww[e] = g_XwWw[((size_t)(t * 4 + w)) * H3 + col];
        }

        gbar((unsigned)(2 * t + 1) * NCTA);

        const float* hp = (t == 0) ? h0 : (out + (size_t)(t - 1) * 1024);
        for (int i = tid; i < 512; i += NTH) sh[i] = hp[i];
        float cprev = 0.f;
        if (tid < Sdim)
            cprev = (t == 0) ? c0[r * Sdim + tid]
                             : out[(size_t)(t - 1) * 1024 + 512 + r * Sdim + tid];
        __syncthreads();

        // 24 dots: 12 gate cols (h@U) + 12 HUw cols (h@Uw)
        if (grp < 24) {
            int d = grp;
            const float* wc = (d < 12) ? (sU + (d << 9)) : (sUw + ((d - 12) << 9));
            float acc = 0.f;
#pragma unroll
            for (int m = 0; m < 16; ++m) {
                int i = m * 32 + lane * 4;
                float4 wv = *reinterpret_cast<const float4*>(wc + i);
                float4 hv = *reinterpret_cast<const float4*>(sh + i);
                acc += wv.x * hv.x + wv.y * hv.y + wv.z * hv.z + wv.w * hv.w;
            }
            acc += __shfl_down_sync(0xffffffffu, acc, 4, 8);
            acc += __shfl_down_sync(0xffffffffu, acc, 2, 8);
            acc += __shfl_down_sync(0xffffffffu, acc, 1, 8);
            if (lane == 0) {
                if (d < 12) sg[d] = sxw[d] + acc;
                else {
                    int dd = d - 12;
                    shuw[dd] = acc;
                    if (t > 0) {
                        int col = (dd >> 2) * 512 + r * Sdim + (dd & 3);
                        g_HUw[(size_t)(t - 1) * H3 + col] = acc;
                    }
                }
            }
        }
        __syncthreads();

        if (tid < 12) {
            float v = sg[tid];
            sg[tid] = (tid >= 8) ? tanhf(v) : 1.f / (1.f + expf(-v));
        }
        if (tid < 16) {
            int w = tid >> 2, jl = tid & 3;
            if (smask[w]) {
                int s = sstart[w];
                int i = r * Sdim + jl;
                float gv[3];
#pragma unroll
                for (int g = 0; g < 3; ++g) {
                    float hu = (s == t - 1) ? shuw[g * Sdim + jl]
                                            : g_HUw[(size_t)s * H3 + g * 512 + i];
                    gv[g] = sxww[w * 12 + g * Sdim + jl] + hu;
                }
                float fw = 1.f / (1.f + expf(-gv[0]));
                float iw = 1.f / (1.f + expf(-gv[1]));
                float gg = tanhf(gv[2]);
                float cs = out[(size_t)s * 1024 + 512 + i];
                g_cw[(w << 9) + i] = fw * cs + iw * gg;
            }
        }

        gbar((unsigned)(2 * t + 2) * NCTA);

        for (int e = tid; e < 2048; e += NTH)
            scw[e] = smask[e >> 9] ? __ldcg(&g_cw[e]) : 0.f;
        __syncthreads();

        // alpha dots: c_w[w] @ Ua col jl
        if (grp < 16) {
            int w = grp >> 2, jl = grp & 3;
            const float* uc = sUa + (jl << 9);
            const float* cc = scw + (w << 9);
            float acc = 0.f;
#pragma unroll
            for (int m = 0; m < 16; ++m) {
                int i = m * 32 + lane * 4;
                float4 wv = *reinterpret_cast<const float4*>(uc + i);
                float4 cv = *reinterpret_cast<const float4*>(cc + i);
                acc += wv.x * cv.x + wv.y * cv.y + wv.z * cv.z + wv.w * cv.w;
            }
            acc += __shfl_down_sync(0xffffffffu, acc, 4, 8);
            acc += __shfl_down_sync(0xffffffffu, acc, 2, 8);
            acc += __shfl_down_sync(0xffffffffu, acc, 1, 8);
            if (lane == 0) salpha[grp] = 1.f / (1.f + expf(-(sxa[jl] + acc)));
        }
        __syncthreads();

        if (tid < Sdim) {
            int j = r * Sdim + tid;
            float ig = sg[tid], og = sg[Sdim + tid], gg = sg[2 * Sdim + tid];
            int any = smask[0] | smask[1] | smask[2] | smask[3];
            float c1;
            if (any) {
                float e0 = expf(ig);
                float den = e0, num = e0 * gg;
#pragma unroll
                for (int w = 0; w < 4; ++w)
                    if (smask[w]) {
                        float ew = expf(salpha[(w << 2) + tid]);
                        den += ew;
                        num += ew * scw[(w << 9) + j];
                    }
                c1 = num / den;
            } else {
                c1 = (1.f - ig) * cprev + ig * gg;
            }
            float h1 = og * tanhf(c1);
            out[(size_t)t * 1024 + j]       = h1;
            out[(size_t)t * 1024 + 512 + j] = c1;
        }
        // no syncthreads needed here: gbar at loop top syncs before sh overwrite
    }
}

extern "C" void kernel_launch(void* const* d_in, const int* in_sizes, int n_in,
                              void* d_out, int out_size) {
    const float* x   = (const float*)d_in[0];
    const int*   wid = (const int*)d_in[1];
    const int*   wst = (const int*)d_in[2];
    const void*  wm  = d_in[3];
    const float* h0  = (const float*)d_in[4];
    const float* c0  = (const float*)d_in[5];
    const float* emb = (const float*)d_in[6];
    const float* W   = (const float*)d_in[7];
    const float* U   = (const float*)d_in[8];
    const float* b   = (const float*)d_in[9];
    const float* Wa  = (const float*)d_in[10];
    const float* Ua  = (const float*)d_in[11];
    const float* ba  = (const float*)d_in[12];
    const float* Ww  = (const float*)d_in[13];
    const float* Uw  = (const float*)d_in[14];
    const float* bw  = (const float*)d_in[15];
    float* out = (float*)d_out;

    void *pXW, *pXWa, *pXwWw;
    cudaGetSymbolAddress(&pXW, g_XW);
    cudaGetSymbolAddress(&pXWa, g_XWa);
    cudaGetSymbolAddress(&pXwWw, g_XwWw);

    cudaFuncSetAttribute(lattice_seq_kernel,
                         cudaFuncAttributeMaxDynamicSharedMemorySize, SMEM_BYTES);

    detect_and_reset<<<1, 256>>>((const unsigned*)wm);
    gemm_bias_kernel<<<dim3(24, 64), 256>>>(x, nullptr, W, b, (float*)pXW, Tt, 128, H3);
    gemm_bias_kernel<<<dim3(8, 64), 256>>>(x, nullptr, Wa, ba, (float*)pXWa, Tt, 128, Hh);
    gemm_bias_kernel<<<dim3(24, 256), 256>>>(emb, wid, Ww, bw, (float*)pXwWw,
                                             Tt * WNw, 256, H3);
    lattice_seq_kernel<<<NCTA, NTH, SMEM_BYTES>>>(h0, c0, wst, wm, U, Ua, Uw, out);
}

// round 4
// speedup vs baseline: 1.2311x; 1.2311x over previous
#include <cuda_runtime.h>
#include <cuda_bf16.h>
#include <cstdint>

#define Tt   4096
#define Hh   512
#define H3   1536
#define WNw  4
#define NCTA 128
#define NTH  256

__device__ float g_XW  [Tt * H3];
__device__ float g_XWa [Tt * Hh];
__device__ float g_XwWw[Tt * WNw * H3];
__device__ float g_cw  [WNw * Hh];
__device__ unsigned g_bar_cw, g_bar_h;
__device__ int g_mask_kind;

// ---- mask dtype detection (u8/i32/f32) + barrier reset ----
__global__ void detect_and_reset(const unsigned* __restrict__ wm) {
    __shared__ int f_gt1, f_f32;
    if (threadIdx.x == 0) { f_gt1 = 0; f_f32 = 0; }
    __syncthreads();
    for (int i = threadIdx.x; i < 4096; i += blockDim.x) {
        unsigned v = wm[i];
        if (v == 0x3F800000u) atomicOr(&f_f32, 1);
        else if (v > 1u)      atomicOr(&f_gt1, 1);
    }
    __syncthreads();
    if (threadIdx.x == 0) {
        g_mask_kind = f_f32 ? 2 : (f_gt1 ? 0 : 1);
        g_bar_cw = 0u; g_bar_h = 0u;
    }
}

// ---- batched GEMM with optional row-gather: C = gather(A)@B + bias ----
#define BM 64
#define BN 64
#define BK 8
__global__ void gemm_bias_kernel(const float* __restrict__ A, const int* __restrict__ idx,
                                 const float* __restrict__ B, const float* __restrict__ bias,
                                 float* __restrict__ C, int M, int K, int N) {
    __shared__ float As[BK][BM];
    __shared__ float Bs[BK][BN];
    const int bm0 = blockIdx.y * BM, bn0 = blockIdx.x * BN;
    const int tid = threadIdx.x;
    const int tx = tid & 15, ty = tid >> 4;
    const int lm = tid >> 2, lkk = (tid & 3) * 2;
    int arow = bm0 + lm;
    if (idx) arow = idx[arow];
    const float* aptr = A + (size_t)arow * K;
    const int bn = tid & 63, bkk = tid >> 6;

    float acc[4][4];
#pragma unroll
    for (int i = 0; i < 4; ++i)
#pragma unroll
        for (int j = 0; j < 4; ++j) acc[i][j] = 0.f;

    for (int k0 = 0; k0 < K; k0 += BK) {
        As[lkk][lm]     = aptr[k0 + lkk];
        As[lkk + 1][lm] = aptr[k0 + lkk + 1];
        Bs[bkk][bn]     = B[(size_t)(k0 + bkk) * N + bn0 + bn];
        Bs[bkk + 4][bn] = B[(size_t)(k0 + bkk + 4) * N + bn0 + bn];
        __syncthreads();
#pragma unroll
        for (int kk = 0; kk < BK; ++kk) {
            float4 av = *reinterpret_cast<const float4*>(&As[kk][ty * 4]);
            float4 bv = *reinterpret_cast<const float4*>(&Bs[kk][tx * 4]);
            float a[4] = {av.x, av.y, av.z, av.w};
            float b4[4] = {bv.x, bv.y, bv.z, bv.w};
#pragma unroll
            for (int i = 0; i < 4; ++i)
#pragma unroll
                for (int j = 0; j < 4; ++j) acc[i][j] += a[i] * b4[j];
        }
        __syncthreads();
    }
#pragma unroll
    for (int i = 0; i < 4; ++i) {
        size_t rbase = (size_t)(bm0 + ty * 4 + i) * N + bn0 + tx * 4;
#pragma unroll
        for (int j = 0; j < 4; ++j)
            C[rbase + j] = acc[i][j] + bias[bn0 + tx * 4 + j];
    }
}

// ---- split-phase grid barrier primitives ----
__device__ __forceinline__ void bar_arrive(unsigned* ctr) {
    asm volatile("red.release.gpu.add.u32 [%0], %1;" :: "l"(ctr), "r"(1u) : "memory");
}
__device__ __forceinline__ void bar_wait(unsigned* ctr, unsigned tgt) {
    unsigned v;
    for (;;) {
        asm volatile("ld.acquire.gpu.u32 %0, [%1];" : "=r"(v) : "l"(ctr) : "memory");
        if (v >= tgt) break;
    }
}

struct CBuf {           // per-step recurrence-independent constants (288 B)
    float xw[12];       // XW cols   (g*4+jl)
    float xa[4];        // XWa cols
    float xww[48];      // XwWw cols (w*12 + g*4 + jl)
    int   mask[4];
    int   start[4];
};

__device__ __forceinline__ float sigf(float v) { return 1.f / (1.f + expf(-v)); }

#define SMEM_FLOATS 6144
#define SMEM_BYTES  (SMEM_FLOATS * 4)

__global__ void __launch_bounds__(NTH, 1)
lattice_seq_kernel(const float* __restrict__ h0, const float* __restrict__ c0,
                   const int* __restrict__ wstarts, const void* __restrict__ wmask,
                   const float* __restrict__ U, const float* __restrict__ Ua,
                   const float* __restrict__ Uw, float* __restrict__ out) {
    extern __shared__ float sm[];
    // init-time overlay: sm[0..6143] = weight staging
    // runtime overlay:
    float4* sh4    = (float4*)sm;            // h_prev  [512]f  (floats 0..511)
    float4* scw4   = (float4*)(sm + 512);    // c_w     [2048]f (floats 512..2559)
    float*  sg     = sm + 2560;              // 12 gates
    float*  salpha = sm + 2576;              // 16
    float*  rc     = sm + 2592;              // ring: own c slice [6][4]
    float*  rhuw   = sm + 2620;              // ring: own huw cols [6][12]
    CBuf*   cbuf   = (CBuf*)(sm + 2700);     // double buffer (16B aligned)

    const int tid = threadIdx.x;
    const int r   = blockIdx.x;
    const int d   = tid >> 3,  l   = tid & 7;    // phase-1: 24 dot groups x 8
    const int g16 = tid >> 4,  l16 = tid & 15;   // alpha: 16 groups x 16
    const int ajl = g16 & 3,   aw  = g16 >> 2;

    // ================= init: weights -> registers (via coalesced smem staging) ===============
    float wreg[64];   // U col slice (d<12) or Uw col slice (12<=d<24)
    float ua[32];     // Ua col slice (all threads)
    {
        for (int e = tid; e < 3 * 512; e += NTH) {
            int gg = e >> 9, i = e & 511;
            float4 v = *reinterpret_cast<const float4*>(&U[(size_t)i * H3 + gg * 512 + r * 4]);
            sm[(gg * 4 + 0) * 512 + i] = v.x; sm[(gg * 4 + 1) * 512 + i] = v.y;
            sm[(gg * 4 + 2) * 512 + i] = v.z; sm[(gg * 4 + 3) * 512 + i] = v.w;
        }
        __syncthreads();
        if (d < 12) {
            int base = d * 512 + l * 4;
#pragma unroll
            for (int m = 0; m < 16; ++m)
#pragma unroll
                for (int k = 0; k < 4; ++k) wreg[m * 4 + k] = sm[base + m * 32 + k];
        }
        __syncthreads();
        for (int e = tid; e < 3 * 512; e += NTH) {
            int gg = e >> 9, i = e & 511;
            float4 v = *reinterpret_cast<const float4*>(&Uw[(size_t)i * H3 + gg * 512 + r * 4]);
            sm[(gg * 4 + 0) * 512 + i] = v.x; sm[(gg * 4 + 1) * 512 + i] = v.y;
            sm[(gg * 4 + 2) * 512 + i] = v.z; sm[(gg * 4 + 3) * 512 + i] = v.w;
        }
        __syncthreads();
        if (d >= 12 && d < 24) {
            int base = (d - 12) * 512 + l * 4;
#pragma unroll
            for (int m = 0; m < 16; ++m)
#pragma unroll
                for (int k = 0; k < 4; ++k) wreg[m * 4 + k] = sm[base + m * 32 + k];
        }
        __syncthreads();
        for (int e = tid; e < 512; e += NTH) {
            float4 v = *reinterpret_cast<const float4*>(&Ua[(size_t)e * Hh + r * 4]);
            sm[0 * 512 + e] = v.x; sm[1 * 512 + e] = v.y;
            sm[2 * 512 + e] = v.z; sm[3 * 512 + e] = v.w;
        }
        __syncthreads();
        {
            int base = ajl * 512 + l16 * 4;
#pragma unroll
            for (int m = 0; m < 8; ++m)
#pragma unroll
                for (int k = 0; k < 4; ++k) ua[m * 4 + k] = sm[base + m * 64 + k];
        }
        __syncthreads();
    }
    const int mk = g_mask_kind;

    // prefetch routine (loads constants of step t1 into buffer t1&1)
    auto prefetch = [&](int t1) {
        CBuf* nb = cbuf + (t1 & 1);
        if (tid >= 32 && tid < 44) {
            int e = tid - 32, w = e / 3, gg = e % 3;
            reinterpret_cast<float4*>(nb->xww)[e] =
                *reinterpret_cast<const float4*>(&g_XwWw[((size_t)(t1 * 4 + w)) * H3 + gg * 512 + r * 4]);
        } else if (tid >= 48 && tid < 51) {
            int gg = tid - 48;
            reinterpret_cast<float4*>(nb->xw)[gg] =
                *reinterpret_cast<const float4*>(&g_XW[(size_t)t1 * H3 + gg * 512 + r * 4]);
        } else if (tid == 51) {
            *reinterpret_cast<float4*>(nb->xa) =
                *reinterpret_cast<const float4*>(&g_XWa[(size_t)t1 * Hh + r * 4]);
        } else if (tid >= 52 && tid < 56) {
            int w = tid - 52, q = t1 * 4 + w;
            int m;
            if (mk == 0)      m = ((const unsigned char*)wmask)[q] != 0;
            else if (mk == 2) m = ((const float*)wmask)[q] != 0.f;
            else              m = ((const int*)wmask)[q] != 0;
            nb->mask[w] = m;
        } else if (tid >= 56 && tid < 60) {
            int w = tid - 56;
            nb->start[w] = wstarts[t1 * 4 + w];
        }
    };

    prefetch(0);
    __syncthreads();

    unsigned cwt = 0;   // local target for the c_w barrier (word-steps only)

    for (int t = 0; t < Tt; ++t) {
        CBuf* cb = cbuf + (t & 1);

        // ---- stage full h_{t-1} ----
        const float4* hp4 = (t == 0) ? (const float4*)h0
                                     : (const float4*)(out + (size_t)(t - 1) * 1024);
        if (tid < 128) sh4[tid] = hp4[tid];
        __syncthreads();

        // ---- 24 dots from registers: 12 gate cols (h@U), 12 huw cols (h@Uw) ----
        if (tid < 192) {
            float a0 = 0.f, a1 = 0.f, a2 = 0.f, a3 = 0.f;
#pragma unroll
            for (int m = 0; m < 16; ++m) {
                float4 hv = sh4[m * 8 + l];
                a0 += wreg[m * 4 + 0] * hv.x;
                a1 += wreg[m * 4 + 1] * hv.y;
                a2 += wreg[m * 4 + 2] * hv.z;
                a3 += wreg[m * 4 + 3] * hv.w;
            }
            float acc = (a0 + a1) + (a2 + a3);
            acc += __shfl_down_sync(0xffffffffu, acc, 4, 8);
            acc += __shfl_down_sync(0xffffffffu, acc, 2, 8);
            acc += __shfl_down_sync(0xffffffffu, acc, 1, 8);
            if (l == 0) {
                if (d < 12) sg[d] = cb->xw[d] + acc;
                else if (t > 0) rhuw[((t - 1) % 6) * 12 + (d - 12)] = acc;
            }
        }
        __syncthreads();

        const int anyw = cb->mask[0] | cb->mask[1] | cb->mask[2] | cb->mask[3];

        // ---- word cells (pure SMEM via rings), publish own c_w slice ----
        if (anyw && tid < 16) {
            int w = tid >> 2, jl = tid & 3;
            if (cb->mask[w]) {
                int s = cb->start[w], slot = (s % 6) * 12;
                float fv = cb->xww[w * 12 + 0 + jl] + rhuw[slot + 0 + jl];
                float iv = cb->xww[w * 12 + 4 + jl] + rhuw[slot + 4 + jl];
                float gv = cb->xww[w * 12 + 8 + jl] + rhuw[slot + 8 + jl];
                float cs = rc[(s % 6) * 4 + jl];
                g_cw[(w << 9) + r * 4 + jl] = sigf(fv) * cs + sigf(iv) * tanhf(gv);
            }
        }
        __syncthreads();
        if (anyw && tid == 0) { __threadfence(); bar_arrive(&g_bar_cw); }

        // ---- overlap window: activations + next-step prefetch ----
        if (tid >= 64 && tid < 76) {
            int dd = tid - 64;
            float v = sg[dd];
            sg[dd] = (dd >= 8) ? tanhf(v) : sigf(v);
        }
        if (t + 1 < Tt) prefetch(t + 1);

        if (anyw) {
            cwt += NCTA;
            if (tid == 0) bar_wait(&g_bar_cw, cwt);
        }
        __syncthreads();

        if (anyw) {
            // ---- stage full c_w: 2048 floats = 512 float4 (L1 bypassed: addrs repeat) ----
            for (int e = tid; e < 512; e += NTH)
                scw4[e] = __ldcg(((const float4*)g_cw) + e);
            __syncthreads();
            // ---- 16 alpha dots (c_w[w] @ Ua col) from registers ----
            {
                float a0 = 0.f, a1 = 0.f, a2 = 0.f, a3 = 0.f;
                const float4* cc4 = scw4 + (aw << 7);
#pragma unroll
                for (int m = 0; m < 8; ++m) {
                    float4 cv = cc4[m * 16 + l16];
                    a0 += ua[m * 4 + 0] * cv.x;
                    a1 += ua[m * 4 + 1] * cv.y;
                    a2 += ua[m * 4 + 2] * cv.z;
                    a3 += ua[m * 4 + 3] * cv.w;
                }
                float acc = (a0 + a1) + (a2 + a3);
                acc += __shfl_down_sync(0xffffffffu, acc, 8, 16);
                acc += __shfl_down_sync(0xffffffffu, acc, 4, 16);
                acc += __shfl_down_sync(0xffffffffu, acc, 2, 16);
                acc += __shfl_down_sync(0xffffffffu, acc, 1, 16);
                if (l16 == 0) salpha[g16] = sigf(cb->xa[ajl] + acc);
            }
            __syncthreads();
        }

        // ---- combine + store outputs ----
        if (tid < 4) {
            int j = r * 4 + tid;
            float ig = sg[tid], og = sg[4 + tid], gg = sg[8 + tid];
            float c1;
            if (anyw) {
                float e0 = expf(ig);
                float den = e0, num = e0 * gg;
#pragma unroll
                for (int w = 0; w < 4; ++w)
                    if (cb->mask[w]) {
                        float ew = expf(salpha[(w << 2) + tid]);
                        den += ew;
                        num += ew * ((const float*)scw4)[(w << 9) + j];
                    }
                c1 = num / den;
            } else {
                float cprev = (t == 0) ? c0[j] : rc[((t - 1) % 6) * 4 + tid];
                c1 = (1.f - ig) * cprev + ig * gg;
            }
            float h1 = og * tanhf(c1);
            out[(size_t)t * 1024 + j]       = h1;
            out[(size_t)t * 1024 + 512 + j] = c1;
            rc[(t % 6) * 4 + tid] = c1;
        }
        __syncthreads();
        if (tid == 0) {
            __threadfence();
            bar_arrive(&g_bar_h);
            bar_wait(&g_bar_h, (unsigned)(t + 1) * NCTA);
        }
        __syncthreads();
    }
}

extern "C" void kernel_launch(void* const* d_in, const int* in_sizes, int n_in,
                              void* d_out, int out_size) {
    const float* x   = (const float*)d_in[0];
    const int*   wid = (const int*)d_in[1];
    const int*   wst = (const int*)d_in[2];
    const void*  wm  = d_in[3];
    const float* h0  = (const float*)d_in[4];
    const float* c0  = (const float*)d_in[5];
    const float* emb = (const float*)d_in[6];
    const float* W   = (const float*)d_in[7];
    const float* U   = (const float*)d_in[8];
    const float* b   = (const float*)d_in[9];
    const float* Wa  = (const float*)d_in[10];
    const float* Ua  = (const float*)d_in[11];
    const float* ba  = (const float*)d_in[12];
    const float* Ww  = (const float*)d_in[13];
    const float* Uw  = (const float*)d_in[14];
    const float* bw  = (const float*)d_in[15];
    float* out = (float*)d_out;

    void *pXW, *pXWa, *pXwWw;
    cudaGetSymbolAddress(&pXW, g_XW);
    cudaGetSymbolAddress(&pXWa, g_XWa);
    cudaGetSymbolAddress(&pXwWw, g_XwWw);

    cudaFuncSetAttribute(lattice_seq_kernel,
                         cudaFuncAttributeMaxDynamicSharedMemorySize, SMEM_BYTES);

    detect_and_reset<<<1, 256>>>((const unsigned*)wm);
    gemm_bias_kernel<<<dim3(24, 64), 256>>>(x, nullptr, W, b, (float*)pXW, Tt, 128, H3);
    gemm_bias_kernel<<<dim3(8, 64), 256>>>(x, nullptr, Wa, ba, (float*)pXWa, Tt, 128, Hh);
    gemm_bias_kernel<<<dim3(24, 256), 256>>>(emb, wid, Ww, bw, (float*)pXwWw,
                                             Tt * WNw, 256, H3);
    lattice_seq_kernel<<<NCTA, NTH, SMEM_BYTES>>>(h0, c0, wst, wm, U, Ua, Uw, out);
}

// round 5
// speedup vs baseline: 1.4611x; 1.1868x over previous
#include <cuda_runtime.h>
#include <cstdint>

#define Tt   4096
#define Hh   512
#define H3   1536
#define NCTA 128
#define NTH  256

__device__ float g_XW  [Tt * H3];
__device__ float g_XWa [Tt * Hh];
__device__ float g_XwWw[Tt * 4 * H3];
__device__ float g_cw  [4 * Hh];
__device__ int   g_maskw[Tt * 4];
__device__ unsigned g_flag_h [NCTA * 64];
__device__ unsigned g_flag_cw[NCTA * 64];
__device__ int g_mask_kind;

// ---- mask dtype detection (u8/i32/f32) ----
__global__ void detect_kernel(const unsigned* __restrict__ wm) {
    __shared__ int f_gt1, f_f32;
    if (threadIdx.x == 0) { f_gt1 = 0; f_f32 = 0; }
    __syncthreads();
    for (int i = threadIdx.x; i < 4096; i += blockDim.x) {
        unsigned v = wm[i];
        if (v == 0x3F800000u) atomicOr(&f_f32, 1);
        else if (v > 1u)      atomicOr(&f_gt1, 1);
    }
    __syncthreads();
    if (threadIdx.x == 0) g_mask_kind = f_f32 ? 2 : (f_gt1 ? 0 : 1);
}

// ---- expand masks to int32 + zero barrier flags ----
__global__ void expand_masks(const void* __restrict__ wm) {
    int i = blockIdx.x * blockDim.x + threadIdx.x;   // 0..16383
    int mk = g_mask_kind;
    int m;
    if (mk == 0)      m = ((const unsigned char*)wm)[i] != 0;
    else if (mk == 2) m = ((const float*)wm)[i] != 0.f;
    else              m = ((const int*)wm)[i] != 0;
    g_maskw[i] = m;
    if (i < NCTA * 64) { g_flag_h[i] = 0u; g_flag_cw[i] = 0u; }
}

// ---- batched GEMM with optional row-gather: C = gather(A)@B + bias ----
#define BM 64
#define BN 64
#define BK 8
__global__ void gemm_bias_kernel(const float* __restrict__ A, const int* __restrict__ idx,
                                 const float* __restrict__ B, const float* __restrict__ bias,
                                 float* __restrict__ C, int M, int K, int N) {
    __shared__ float As[BK][BM];
    __shared__ float Bs[BK][BN];
    const int bm0 = blockIdx.y * BM, bn0 = blockIdx.x * BN;
    const int tid = threadIdx.x;
    const int tx = tid & 15, ty = tid >> 4;
    const int lm = tid >> 2, lkk = (tid & 3) * 2;
    int arow = bm0 + lm;
    if (idx) arow = idx[arow];
    const float* aptr = A + (size_t)arow * K;
    const int bn = tid & 63, bkk = tid >> 6;

    float acc[4][4];
#pragma unroll
    for (int i = 0; i < 4; ++i)
#pragma unroll
        for (int j = 0; j < 4; ++j) acc[i][j] = 0.f;

    for (int k0 = 0; k0 < K; k0 += BK) {
        As[lkk][lm]     = aptr[k0 + lkk];
        As[lkk + 1][lm] = aptr[k0 + lkk + 1];
        Bs[bkk][bn]     = B[(size_t)(k0 + bkk) * N + bn0 + bn];
        Bs[bkk + 4][bn] = B[(size_t)(k0 + bkk + 4) * N + bn0 + bn];
        __syncthreads();
#pragma unroll
        for (int kk = 0; kk < BK; ++kk) {
            float4 av = *reinterpret_cast<const float4*>(&As[kk][ty * 4]);
            float4 bv = *reinterpret_cast<const float4*>(&Bs[kk][tx * 4]);
            float a[4] = {av.x, av.y, av.z, av.w};
            float b4[4] = {bv.x, bv.y, bv.z, bv.w};
#pragma unroll
            for (int i = 0; i < 4; ++i)
#pragma unroll
                for (int j = 0; j < 4; ++j) acc[i][j] += a[i] * b4[j];
        }
        __syncthreads();
    }
#pragma unroll
    for (int i = 0; i < 4; ++i) {
        size_t rbase = (size_t)(bm0 + ty * 4 + i) * N + bn0 + tx * 4;
#pragma unroll
        for (int j = 0; j < 4; ++j)
            C[rbase + j] = acc[i][j] + bias[bn0 + tx * 4 + j];
    }
}

// ---- contention-free flag barrier primitives ----
__device__ __forceinline__ void flag_post(unsigned* slot, unsigned epoch) {
    asm volatile("st.release.gpu.u32 [%0], %1;" :: "l"(slot), "r"(epoch) : "memory");
}
__device__ __forceinline__ void flag_wait(const unsigned* slot, unsigned epoch) {
    unsigned v;
    do {
        asm volatile("ld.acquire.gpu.u32 %0, [%1];" : "=r"(v) : "l"(slot) : "memory");
    } while (v < epoch);
}

// ---- cp.async helpers ----
__device__ __forceinline__ void cp16(uint32_t saddr, const void* g) {
    asm volatile("cp.async.cg.shared.global [%0], [%1], 16;" :: "r"(saddr), "l"(g) : "memory");
}
__device__ __forceinline__ void cp_commit() {
    asm volatile("cp.async.commit_group;" ::: "memory");
}
__device__ __forceinline__ void cp_wait0() {
    asm volatile("cp.async.wait_group 0;" ::: "memory");
}

struct CBuf {           // 288 B, 16B-aligned fields
    float xw[12];       // XW cols   (g*4+jl)
    float xa[4];        // XWa cols
    float xww[48];      // XwWw cols (w*12 + g*4 + jl)
    int   mask[4];
    int   start[4];
};

__device__ __forceinline__ float sigf(float v) { return 1.f / (1.f + expf(-v)); }

#define SMEM_FLOATS 6144
#define SMEM_BYTES  (SMEM_FLOATS * 4)

__global__ void __launch_bounds__(NTH, 1)
lattice_seq_kernel(const float* __restrict__ h0, const float* __restrict__ c0,
                   const int* __restrict__ wstarts,
                   const float* __restrict__ U, const float* __restrict__ Ua,
                   const float* __restrict__ Uw, float* __restrict__ out) {
    extern __shared__ float sm[];
    float4* sh4    = (float4*)sm;            // h_prev  [512]f
    float4* scw4   = (float4*)(sm + 512);    // c_w     [2048]f
    float*  sg     = sm + 2560;              // 12 gates
    float*  salpha = sm + 2576;              // 16
    float*  rc     = sm + 2592;              // ring: own c slice [6][4]
    float*  rhuw   = sm + 2620;              // ring: own huw cols [6][12]
    CBuf*   cbuf   = (CBuf*)(sm + 2700);     // double buffer

    const int tid = threadIdx.x;
    const int r   = blockIdx.x;
    const int d   = tid >> 3,  l   = tid & 7;
    const int g16 = tid >> 4,  l16 = tid & 15;
    const int ajl = g16 & 3,   aw  = g16 >> 2;

    // ========== init: weights -> registers via coalesced SMEM staging ==========
    float wreg[64];   // U col slice (d<12) or Uw col slice (12<=d<24)
    float ua[32];     // Ua col slice
    {
        for (int e = tid; e < 3 * 512; e += NTH) {
            int gg = e >> 9, i = e & 511;
            float4 v = *reinterpret_cast<const float4*>(&U[(size_t)i * H3 + gg * 512 + r * 4]);
            sm[(gg * 4 + 0) * 512 + i] = v.x; sm[(gg * 4 + 1) * 512 + i] = v.y;
            sm[(gg * 4 + 2) * 512 + i] = v.z; sm[(gg * 4 + 3) * 512 + i] = v.w;
        }
        __syncthreads();
        if (d < 12) {
            int base = d * 512 + l * 4;
#pragma unroll
            for (int m = 0; m < 16; ++m)
#pragma unroll
                for (int k = 0; k < 4; ++k) wreg[m * 4 + k] = sm[base + m * 32 + k];
        }
        __syncthreads();
        for (int e = tid; e < 3 * 512; e += NTH) {
            int gg = e >> 9, i = e & 511;
            float4 v = *reinterpret_cast<const float4*>(&Uw[(size_t)i * H3 + gg * 512 + r * 4]);
            sm[(gg * 4 + 0) * 512 + i] = v.x; sm[(gg * 4 + 1) * 512 + i] = v.y;
            sm[(gg * 4 + 2) * 512 + i] = v.z; sm[(gg * 4 + 3) * 512 + i] = v.w;
        }
        __syncthreads();
        if (d >= 12 && d < 24) {
            int base = (d - 12) * 512 + l * 4;
#pragma unroll
            for (int m = 0; m < 16; ++m)
#pragma unroll
                for (int k = 0; k < 4; ++k) wreg[m * 4 + k] = sm[base + m * 32 + k];
        }
        __syncthreads();
        for (int e = tid; e < 512; e += NTH) {
            float4 v = *reinterpret_cast<const float4*>(&Ua[(size_t)e * Hh + r * 4]);
            sm[0 * 512 + e] = v.x; sm[1 * 512 + e] = v.y;
            sm[2 * 512 + e] = v.z; sm[3 * 512 + e] = v.w;
        }
        __syncthreads();
        {
            int base = ajl * 512 + l16 * 4;
#pragma unroll
            for (int m = 0; m < 8; ++m)
#pragma unroll
                for (int k = 0; k < 4; ++k) ua[m * 4 + k] = sm[base + m * 64 + k];
        }
        __syncthreads();
    }

    // cp.async prefetch of step t1 constants into cbuf[t1&1] (threads 160..177)
    auto issue_prefetch = [&](int t1) {
        CBuf* nb = cbuf + (t1 & 1);
        int e = tid - 160;
        if (e >= 0 && e < 18) {
            const void* src;
            uint32_t dst;
            if (e < 12) {
                int w = e / 3, gg = e % 3;
                src = &g_XwWw[((size_t)(t1 * 4 + w)) * H3 + gg * 512 + r * 4];
                dst = (uint32_t)__cvta_generic_to_shared(&nb->xww[e * 4]);
            } else if (e < 15) {
                int gg = e - 12;
                src = &g_XW[(size_t)t1 * H3 + gg * 512 + r * 4];
                dst = (uint32_t)__cvta_generic_to_shared(&nb->xw[gg * 4]);
            } else if (e == 15) {
                src = &g_XWa[(size_t)t1 * Hh + r * 4];
                dst = (uint32_t)__cvta_generic_to_shared(nb->xa);
            } else if (e == 16) {
                src = &wstarts[t1 * 4];
                dst = (uint32_t)__cvta_generic_to_shared(nb->start);
            } else {
                src = &g_maskw[t1 * 4];
                dst = (uint32_t)__cvta_generic_to_shared(nb->mask);
            }
            cp16(dst, src);
        }
        if (tid >= 160 && tid < 192) cp_commit();
    };

    // prime step 0 constants
    issue_prefetch(0);
    if (tid >= 160 && tid < 192) cp_wait0();
    __syncthreads();

    unsigned cwt = 0;

    for (int t = 0; t < Tt; ++t) {
        CBuf* cb = cbuf + (t & 1);

        // issue next step's prefetch (non-blocking, waited at step end)
        if (t + 1 < Tt) issue_prefetch(t + 1);

        // ---- stage full h_{t-1} ----
        const float4* hp4 = (t == 0) ? (const float4*)h0
                                     : (const float4*)(out + (size_t)(t - 1) * 1024);
        if (tid < 128) sh4[tid] = hp4[tid];
        __syncthreads();

        // ---- 24 dots from registers: 12 gate cols (h@U), 12 huw cols (h@Uw) ----
        if (tid < 192) {
            float a0 = 0.f, a1 = 0.f, a2 = 0.f, a3 = 0.f;
#pragma unroll
            for (int m = 0; m < 16; ++m) {
                float4 hv = sh4[m * 8 + l];
                a0 += wreg[m * 4 + 0] * hv.x;
                a1 += wreg[m * 4 + 1] * hv.y;
                a2 += wreg[m * 4 + 2] * hv.z;
                a3 += wreg[m * 4 + 3] * hv.w;
            }
            float acc = (a0 + a1) + (a2 + a3);
            acc += __shfl_down_sync(0xffffffffu, acc, 4, 8);
            acc += __shfl_down_sync(0xffffffffu, acc, 2, 8);
            acc += __shfl_down_sync(0xffffffffu, acc, 1, 8);
            if (l == 0) {
                if (d < 12) sg[d] = cb->xw[d] + acc;
                else if (t > 0) rhuw[((t - 1) % 6) * 12 + (d - 12)] = acc;
            }
        }
        __syncthreads();

        const int anyw = cb->mask[0] | cb->mask[1] | cb->mask[2] | cb->mask[3];

        if (anyw) {
            cwt++;
            // word cells (pure SMEM rings), publish own c_w slice
            if (tid < 16) {
                int w = tid >> 2, jl = tid & 3;
                if (cb->mask[w]) {
                    int s = cb->start[w], slot = (s % 6) * 12;
                    float fv = cb->xww[w * 12 + 0 + jl] + rhuw[slot + 0 + jl];
                    float iv = cb->xww[w * 12 + 4 + jl] + rhuw[slot + 4 + jl];
                    float gv = cb->xww[w * 12 + 8 + jl] + rhuw[slot + 8 + jl];
                    float cs = rc[(s % 6) * 4 + jl];
                    g_cw[(w << 9) + r * 4 + jl] = sigf(fv) * cs + sigf(iv) * tanhf(gv);
                }
            }
            __syncthreads();
            if (tid == 0) flag_post(&g_flag_cw[r * 64], cwt);
        }

        // overlap: gate activations (threads 128-139, not pollers)
        if (tid >= 128 && tid < 140) {
            int dd = tid - 128;
            float v = sg[dd];
            sg[dd] = (dd >= 8) ? tanhf(v) : sigf(v);
        }

        if (anyw) {
            if (tid < NCTA) flag_wait(&g_flag_cw[tid * 64], cwt);
            __syncthreads();
            // stage full c_w: 512 float4 (L1 bypassed: addresses repeat)
            for (int e = tid; e < 512; e += NTH)
                scw4[e] = __ldcg(((const float4*)g_cw) + e);
            __syncthreads();
            // 16 alpha dots (c_w[w] @ Ua col) from registers
            {
                float a0 = 0.f, a1 = 0.f, a2 = 0.f, a3 = 0.f;
                const float4* cc4 = scw4 + (aw << 7);
#pragma unroll
                for (int m = 0; m < 8; ++m) {
                    float4 cv = cc4[m * 16 + l16];
                    a0 += ua[m * 4 + 0] * cv.x;
                    a1 += ua[m * 4 + 1] * cv.y;
                    a2 += ua[m * 4 + 2] * cv.z;
                    a3 += ua[m * 4 + 3] * cv.w;
                }
                float acc = (a0 + a1) + (a2 + a3);
                acc += __shfl_down_sync(0xffffffffu, acc, 8, 16);
                acc += __shfl_down_sync(0xffffffffu, acc, 4, 16);
                acc += __shfl_down_sync(0xffffffffu, acc, 2, 16);
                acc += __shfl_down_sync(0xffffffffu, acc, 1, 16);
                if (l16 == 0) salpha[g16] = sigf(cb->xa[ajl] + acc);
            }
            __syncthreads();
        } else {
            __syncthreads();   // publish activations for combine
        }

        // ---- combine + store outputs ----
        if (tid < 4) {
            int j = r * 4 + tid;
            float ig = sg[tid], og = sg[4 + tid], gg = sg[8 + tid];
            float c1;
            if (anyw) {
                float e0 = expf(ig);
                float den = e0, num = e0 * gg;
#pragma unroll
                for (int w = 0; w < 4; ++w)
                    if (cb->mask[w]) {
                        float ew = expf(salpha[(w << 2) + tid]);
                        den += ew;
                        num += ew * ((const float*)scw4)[(w << 9) + j];
                    }
                c1 = num / den;
            } else {
                float cprev = (t == 0) ? c0[j] : rc[((t - 1) % 6) * 4 + tid];
                c1 = (1.f - ig) * cprev + ig * gg;
            }
            float h1 = og * tanhf(c1);
            out[(size_t)t * 1024 + j]       = h1;
            out[(size_t)t * 1024 + 512 + j] = c1;
            rc[(t % 6) * 4 + tid] = c1;
        }

        // ---- h barrier (flag-array) + cp.async drain in parallel ----
        __syncthreads();
        if (tid == 0) flag_post(&g_flag_h[r * 64], (unsigned)(t + 1));
        if (tid >= 160 && tid < 192) cp_wait0();
        if (tid < NCTA) flag_wait(&g_flag_h[tid * 64], (unsigned)(t + 1));
        __syncthreads();
    }
}

extern "C" void kernel_launch(void* const* d_in, const int* in_sizes, int n_in,
                              void* d_out, int out_size) {
    const float* x   = (const float*)d_in[0];
    const int*   wid = (const int*)d_in[1];
    const int*   wst = (const int*)d_in[2];
    const void*  wm  = d_in[3];
    const float* h0  = (const float*)d_in[4];
    const float* c0  = (const float*)d_in[5];
    const float* emb = (const float*)d_in[6];
    const float* W   = (const float*)d_in[7];
    const float* U   = (const float*)d_in[8];
    const float* b   = (const float*)d_in[9];
    const float* Wa  = (const float*)d_in[10];
    const float* Ua  = (const float*)d_in[11];
    const float* ba  = (const float*)d_in[12];
    const float* Ww  = (const float*)d_in[13];
    const float* Uw  = (const float*)d_in[14];
    const float* bw  = (const float*)d_in[15];
    float* out = (float*)d_out;

    void *pXW, *pXWa, *pXwWw;
    cudaGetSymbolAddress(&pXW, g_XW);
    cudaGetSymbolAddress(&pXWa, g_XWa);
    cudaGetSymbolAddress(&pXwWw, g_XwWw);

    cudaFuncSetAttribute(lattice_seq_kernel,
                         cudaFuncAttributeMaxDynamicSharedMemorySize, SMEM_BYTES);

    detect_kernel<<<1, 256>>>((const unsigned*)wm);
    expand_masks<<<64, 256>>>(wm);
    gemm_bias_kernel<<<dim3(24, 64), 256>>>(x, nullptr, W, b, (float*)pXW, Tt, 128, H3);
    gemm_bias_kernel<<<dim3(8, 64), 256>>>(x, nullptr, Wa, ba, (float*)pXWa, Tt, 128, Hh);
    gemm_bias_kernel<<<dim3(24, 256), 256>>>(emb, wid, Ww, bw, (float*)pXwWw,
                                             Tt * 4, 256, H3);
    lattice_seq_kernel<<<NCTA, NTH, SMEM_BYTES>>>(h0, c0, wst, U, Ua, Uw, out);
}

// round 7
// speedup vs baseline: 1.5447x; 1.0572x over previous
#include <cuda_runtime.h>
#include <cstdint>

#define Tt   4096
#define Hh   512
#define H3   1536
#define NCTA 128
#define NTH  256

__device__ float g_XW  [Tt * H3];
__device__ float g_XWa [Tt * Hh];
__device__ float g_XwWw[Tt * 4 * H3];
__device__ float g_cw  [2][4 * Hh];
__device__ int   g_maskw[Tt * 4];
__device__ unsigned g_flag_h [NCTA * 64];
__device__ unsigned g_flag_cw[NCTA * 64];
__device__ int g_mask_kind;

// ---- mask dtype detection (u8/i32/f32) ----
__global__ void detect_kernel(const unsigned* __restrict__ wm) {
    __shared__ int f_gt1, f_f32;
    if (threadIdx.x == 0) { f_gt1 = 0; f_f32 = 0; }
    __syncthreads();
    for (int i = threadIdx.x; i < 4096; i += blockDim.x) {
        unsigned v = wm[i];
        if (v == 0x3F800000u) atomicOr(&f_f32, 1);
        else if (v > 1u)      atomicOr(&f_gt1, 1);
    }
    __syncthreads();
    if (threadIdx.x == 0) g_mask_kind = f_f32 ? 2 : (f_gt1 ? 0 : 1);
}

// ---- expand masks to int32 + zero barrier flags ----
__global__ void expand_masks(const void* __restrict__ wm) {
    int i = blockIdx.x * blockDim.x + threadIdx.x;   // 0..16383
    int mk = g_mask_kind;
    int m;
    if (mk == 0)      m = ((const unsigned char*)wm)[i] != 0;
    else if (mk == 2) m = ((const float*)wm)[i] != 0.f;
    else              m = ((const int*)wm)[i] != 0;
    g_maskw[i] = m;
    if (i < NCTA * 64) { g_flag_h[i] = 0u; g_flag_cw[i] = 0u; }
}

// ---- batched GEMM with optional row-gather: C = gather(A)@B + bias ----
#define BM 64
#define BN 64
#define BK 8
__global__ void gemm_bias_kernel(const float* __restrict__ A, const int* __restrict__ idx,
                                 const float* __restrict__ B, const float* __restrict__ bias,
                                 float* __restrict__ C, int M, int K, int N) {
    __shared__ float As[BK][BM];
    __shared__ float Bs[BK][BN];
    const int bm0 = blockIdx.y * BM, bn0 = blockIdx.x * BN;
    const int tid = threadIdx.x;
    const int tx = tid & 15, ty = tid >> 4;
    const int lm = tid >> 2, lkk = (tid & 3) * 2;
    int arow = bm0 + lm;
    if (idx) arow = idx[arow];
    const float* aptr = A + (size_t)arow * K;
    const int bn = tid & 63, bkk = tid >> 6;

    float acc[4][4];
#pragma unroll
    for (int i = 0; i < 4; ++i)
#pragma unroll
        for (int j = 0; j < 4; ++j) acc[i][j] = 0.f;

    for (int k0 = 0; k0 < K; k0 += BK) {
        As[lkk][lm]     = aptr[k0 + lkk];
        As[lkk + 1][lm] = aptr[k0 + lkk + 1];
        Bs[bkk][bn]     = B[(size_t)(k0 + bkk) * N + bn0 + bn];
        Bs[bkk + 4][bn] = B[(size_t)(k0 + bkk + 4) * N + bn0 + bn];
        __syncthreads();
#pragma unroll
        for (int kk = 0; kk < BK; ++kk) {
            float4 av = *reinterpret_cast<const float4*>(&As[kk][ty * 4]);
            float4 bv = *reinterpret_cast<const float4*>(&Bs[kk][tx * 4]);
            float a[4] = {av.x, av.y, av.z, av.w};
            float b4[4] = {bv.x, bv.y, bv.z, bv.w};
#pragma unroll
            for (int i = 0; i < 4; ++i)
#pragma unroll
                for (int j = 0; j < 4; ++j) acc[i][j] += a[i] * b4[j];
        }
        __syncthreads();
    }
#pragma unroll
    for (int i = 0; i < 4; ++i) {
        size_t rbase = (size_t)(bm0 + ty * 4 + i) * N + bn0 + tx * 4;
#pragma unroll
        for (int j = 0; j < 4; ++j)
            C[rbase + j] = acc[i][j] + bias[bn0 + tx * 4 + j];
    }
}

// ---- contention-free flag barrier primitives ----
__device__ __forceinline__ void flag_post(unsigned* slot, unsigned epoch) {
    asm volatile("st.release.gpu.u32 [%0], %1;" :: "l"(slot), "r"(epoch) : "memory");
}
__device__ __forceinline__ void flag_wait(const unsigned* slot, unsigned epoch) {
    unsigned v;
    do {
        asm volatile("ld.acquire.gpu.u32 %0, [%1];" : "=r"(v) : "l"(slot) : "memory");
    } while (v < epoch);
}

// ---- cp.async helpers ----
__device__ __forceinline__ void cp16(uint32_t saddr, const void* g) {
    asm volatile("cp.async.cg.shared.global [%0], [%1], 16;" :: "r"(saddr), "l"(g) : "memory");
}
__device__ __forceinline__ void cp_commit() {
    asm volatile("cp.async.commit_group;" ::: "memory");
}
__device__ __forceinline__ void cp_wait0() {
    asm volatile("cp.async.wait_group 0;" ::: "memory");
}

struct CBuf {           // 288 B, 16B-aligned fields
    float xw[12];       // XW cols   (g*4+jl)
    float xa[4];        // XWa cols
    float xww[48];      // XwWw cols (w*12 + g*4 + jl)
    int   mask[4];
    int   start[4];
};

__device__ __forceinline__ float sigf(float v) { return 1.f / (1.f + expf(-v)); }

#define SMEM_FLOATS 6144
#define SMEM_BYTES  (SMEM_FLOATS * 4)

__global__ void __launch_bounds__(NTH, 1)
lattice_seq_kernel(const float* __restrict__ h0, const float* __restrict__ c0,
                   const int* __restrict__ wstarts,
                   const float* __restrict__ U, const float* __restrict__ Ua,
                   const float* __restrict__ Uw, float* __restrict__ out) {
    extern __shared__ float sm[];
    float4* sh4    = (float4*)sm;            // h_prev  [512]f
    float4* scw4   = (float4*)(sm + 512);    // c_w     [2048]f
    float*  sg     = sm + 2560;              // 12 gates
    float*  salpha = sm + 2576;              // 16
    float*  rc     = sm + 2592;              // ring: own c slice [6][4]
    float*  rhuw   = sm + 2620;              // ring: own huw cols [6][12]
    CBuf*   cbuf   = (CBuf*)(sm + 2704);     // triple buffer (16B aligned)

    const int tid = threadIdx.x;
    const int r   = blockIdx.x;
    const int d   = tid >> 3,  l   = tid & 7;
    const int g16 = tid >> 4,  l16 = tid & 15;
    const int ajl = g16 & 3,   aw  = g16 >> 2;

    // ========== init: weights -> registers via coalesced SMEM staging ==========
    float wreg[64];   // U col slice (d<12) or Uw col slice (12<=d<24)
    float ua[32];     // Ua col slice
    {
        for (int e = tid; e < 3 * 512; e += NTH) {
            int gg = e >> 9, i = e & 511;
            float4 v = *reinterpret_cast<const float4*>(&U[(size_t)i * H3 + gg * 512 + r * 4]);
            sm[(gg * 4 + 0) * 512 + i] = v.x; sm[(gg * 4 + 1) * 512 + i] = v.y;
            sm[(gg * 4 + 2) * 512 + i] = v.z; sm[(gg * 4 + 3) * 512 + i] = v.w;
        }
        __syncthreads();
        if (d < 12) {
            int base = d * 512 + l * 4;
#pragma unroll
            for (int m = 0; m < 16; ++m)
#pragma unroll
                for (int k = 0; k < 4; ++k) wreg[m * 4 + k] = sm[base + m * 32 + k];
        }
        __syncthreads();
        for (int e = tid; e < 3 * 512; e += NTH) {
            int gg = e >> 9, i = e & 511;
            float4 v = *reinterpret_cast<const float4*>(&Uw[(size_t)i * H3 + gg * 512 + r * 4]);
            sm[(gg * 4 + 0) * 512 + i] = v.x; sm[(gg * 4 + 1) * 512 + i] = v.y;
            sm[(gg * 4 + 2) * 512 + i] = v.z; sm[(gg * 4 + 3) * 512 + i] = v.w;
        }
        __syncthreads();
        if (d >= 12 && d < 24) {
            int base = (d - 12) * 512 + l * 4;
#pragma unroll
            for (int m = 0; m < 16; ++m)
#pragma unroll
                for (int k = 0; k < 4; ++k) wreg[m * 4 + k] = sm[base + m * 32 + k];
        }
        __syncthreads();
        for (int e = tid; e < 512; e += NTH) {
            float4 v = *reinterpret_cast<const float4*>(&Ua[(size_t)e * Hh + r * 4]);
            sm[0 * 512 + e] = v.x; sm[1 * 512 + e] = v.y;
            sm[2 * 512 + e] = v.z; sm[3 * 512 + e] = v.w;
        }
        __syncthreads();
        {
            int base = ajl * 512 + l16 * 4;
#pragma unroll
            for (int m = 0; m < 8; ++m)
#pragma unroll
                for (int k = 0; k < 4; ++k) ua[m * 4 + k] = sm[base + m * 64 + k];
        }
        __syncthreads();
    }

    // cp.async prefetch of step t1 constants into cbuf[t1%3] (threads 160..177)
    auto issue_prefetch = [&](int t1) {
        CBuf* nb = cbuf + (t1 % 3);
        int e = tid - 160;
        if (e >= 0 && e < 18) {
            const void* src;
            uint32_t dst;
            if (e < 12) {
                int w = e / 3, gg = e % 3;
                src = &g_XwWw[((size_t)(t1 * 4 + w)) * H3 + gg * 512 + r * 4];
                dst = (uint32_t)__cvta_generic_to_shared(&nb->xww[e * 4]);
            } else if (e < 15) {
                int gg = e - 12;
                src = &g_XW[(size_t)t1 * H3 + gg * 512 + r * 4];
                dst = (uint32_t)__cvta_generic_to_shared(&nb->xw[gg * 4]);
            } else if (e == 15) {
                src = &g_XWa[(size_t)t1 * Hh + r * 4];
                dst = (uint32_t)__cvta_generic_to_shared(nb->xa);
            } else if (e == 16) {
                src = &wstarts[t1 * 4];
                dst = (uint32_t)__cvta_generic_to_shared(nb->start);
            } else {
                src = &g_maskw[t1 * 4];
                dst = (uint32_t)__cvta_generic_to_shared(nb->mask);
            }
            cp16(dst, src);
        }
        if (tid >= 160 && tid < 192) cp_commit();
    };

    // prime step 0 and step 1 constants
    issue_prefetch(0);
    issue_prefetch(1);
    if (tid >= 160 && tid < 192) cp_wait0();
    __syncthreads();

    unsigned lt = 0;   // late-step epoch (identical across CTAs)

    for (int t = 0; t < Tt; ++t) {
        CBuf* cb = cbuf + (t % 3);
        CBuf* nb = cbuf + ((t + 1) % 3);

        const int anyw = cb->mask[0] | cb->mask[1] | cb->mask[2] | cb->mask[3];
        int haslate = 0;
#pragma unroll
        for (int w = 0; w < 4; ++w)
            haslate |= cb->mask[w] & (cb->start[w] == t - 1);
        if (haslate) ++lt;

        // issue prefetch for step t+2 (waited at end of step)
        if (t + 2 < Tt) issue_prefetch(t + 2);

        // ---- stage h_{t-1}; on no-late word steps also stage c_w (synced by h barrier) ----
        const float4* hp4 = (t == 0) ? (const float4*)h0
                                     : (const float4*)(out + (size_t)(t - 1) * 1024);
        if (tid < 128) sh4[tid] = hp4[tid];
        else if (anyw && !haslate) {
            const float4* src = (const float4*)g_cw[t & 1];
            for (int e = tid - 128; e < 512; e += 128)
                scw4[e] = __ldcg(src + e);
        }
        __syncthreads();

        // ---- 24 dots from registers: 12 gate cols (h@U), 12 huw cols (h@Uw) ----
        if (tid < 192) {
            float a0 = 0.f, a1 = 0.f, a2 = 0.f, a3 = 0.f;
#pragma unroll
            for (int m = 0; m < 16; ++m) {
                float4 hv = sh4[m * 8 + l];
                a0 += wreg[m * 4 + 0] * hv.x;
                a1 += wreg[m * 4 + 1] * hv.y;
                a2 += wreg[m * 4 + 2] * hv.z;
                a3 += wreg[m * 4 + 3] * hv.w;
            }
            float acc = (a0 + a1) + (a2 + a3);
            acc += __shfl_down_sync(0xffffffffu, acc, 4, 8);
            acc += __shfl_down_sync(0xffffffffu, acc, 2, 8);
            acc += __shfl_down_sync(0xffffffffu, acc, 1, 8);
            if (l == 0) {
                if (d < 12) sg[d] = cb->xw[d] + acc;
                else if (t > 0) rhuw[((t - 1) % 6) * 12 + (d - 12)] = acc;
            }
        }
        __syncthreads();

        // ---- late words of step t (start == t-1) -> g_cw[t&1] ----
        if (haslate && tid < 16) {
            int w = tid >> 2, jl = tid & 3;
            if (cb->mask[w] && cb->start[w] == t - 1) {
                int s = cb->start[w], slot = (s % 6) * 12;
                float fv = cb->xww[w * 12 + 0 + jl] + rhuw[slot + 0 + jl];
                float iv = cb->xww[w * 12 + 4 + jl] + rhuw[slot + 4 + jl];
                float gv = cb->xww[w * 12 + 8 + jl] + rhuw[slot + 8 + jl];
                float cs = rc[(s % 6) * 4 + jl];
                g_cw[t & 1][(w << 9) + r * 4 + jl] = sigf(fv) * cs + sigf(iv) * tanhf(gv);
            }
        }
        // ---- early words of step t+1 (start <= t-1) -> g_cw[(t+1)&1] (synced by h barrier) ----
        if (tid >= 16 && tid < 32 && t + 1 < Tt) {
            int w = (tid - 16) >> 2, jl = tid & 3;
            if (nb->mask[w] && nb->start[w] != t) {
                int s = nb->start[w], slot = (s % 6) * 12;
                float fv = nb->xww[w * 12 + 0 + jl] + rhuw[slot + 0 + jl];
                float iv = nb->xww[w * 12 + 4 + jl] + rhuw[slot + 4 + jl];
                float gv = nb->xww[w * 12 + 8 + jl] + rhuw[slot + 8 + jl];
                float cs = rc[(s % 6) * 4 + jl];
                g_cw[(t + 1) & 1][(w << 9) + r * 4 + jl] = sigf(fv) * cs + sigf(iv) * tanhf(gv);
            }
        }
        // ---- gate activations (threads 128-139, not barrier pollers) ----
        if (tid >= 128 && tid < 140) {
            int dd = tid - 128;
            float v = sg[dd];
            sg[dd] = (dd >= 8) ? tanhf(v) : sigf(v);
        }

        if (haslate) {
            __syncthreads();    // late writes done before flag
            if (tid == 0) flag_post(&g_flag_cw[r * 64], lt);
            if (tid < NCTA) flag_wait(&g_flag_cw[tid * 64], lt);
            __syncthreads();
            const float4* src = (const float4*)g_cw[t & 1];
            for (int e = tid; e < 512; e += NTH)
                scw4[e] = __ldcg(src + e);
            __syncthreads();
        } else {
            __syncthreads();    // publish activations (+scw already staged)
        }

        // ---- 16 alpha dots (c_w[w] @ Ua col) from registers ----
        if (anyw) {
            float a0 = 0.f, a1 = 0.f, a2 = 0.f, a3 = 0.f;
            const float4* cc4 = scw4 + (aw << 7);
#pragma unroll
            for (int m = 0; m < 8; ++m) {
                float4 cv = cc4[m * 16 + l16];
                a0 += ua[m * 4 + 0] * cv.x;
                a1 += ua[m * 4 + 1] * cv.y;
                a2 += ua[m * 4 + 2] * cv.z;
                a3 += ua[m * 4 + 3] * cv.w;
            }
            float acc = (a0 + a1) + (a2 + a3);
            acc += __shfl_down_sync(0xffffffffu, acc, 8, 16);
            acc += __shfl_down_sync(0xffffffffu, acc, 4, 16);
            acc += __shfl_down_sync(0xffffffffu, acc, 2, 16);
            acc += __shfl_down_sync(0xffffffffu, acc, 1, 16);
            if (l16 == 0) salpha[g16] = sigf(cb->xa[ajl] + acc);
            __syncthreads();
        }

        // ---- combine + store outputs ----
        if (tid < 4) {
            int j = r * 4 + tid;
            float ig = sg[tid], og = sg[4 + tid], gg = sg[8 + tid];
            float c1;
            if (anyw) {
                float e0 = expf(ig);
                float den = e0, num = e0 * gg;
#pragma unroll
                for (int w = 0; w < 4; ++w)
                    if (cb->mask[w]) {
                        float ew = expf(salpha[(w << 2) + tid]);
                        den += ew;
                        num += ew * ((const float*)scw4)[(w << 9) + j];
                    }
                c1 = num / den;
            } else {
                float cprev = (t == 0) ? c0[j] : rc[((t - 1) % 6) * 4 + tid];
                c1 = (1.f - ig) * cprev + ig * gg;
            }
            float h1 = og * tanhf(c1);
            out[(size_t)t * 1024 + j]       = h1;
            out[(size_t)t * 1024 + 512 + j] = c1;
            rc[(t % 6) * 4 + tid] = c1;
        }

        // ---- h barrier (flag-array) + cp.async drain in parallel ----
        __syncthreads();
        if (tid == 0) flag_post(&g_flag_h[r * 64], (unsigned)(t + 1));
        if (tid >= 160 && tid < 192) cp_wait0();
        if (tid < NCTA) flag_wait(&g_flag_h[tid * 64], (unsigned)(t + 1));
        __syncthreads();
    }
}

extern "C" void kernel_launch(void* const* d_in, const int* in_sizes, int n_in,
                              void* d_out, int out_size) {
    const float* x   = (const float*)d_in[0];
    const int*   wid = (const int*)d_in[1];
    const int*   wst = (const int*)d_in[2];
    const void*  wm  = d_in[3];
    const float* h0  = (const float*)d_in[4];
    const float* c0  = (const float*)d_in[5];
    const float* emb = (const float*)d_in[6];
    const float* W   = (const float*)d_in[7];
    const float* U   = (const float*)d_in[8];
    const float* b   = (const float*)d_in[9];
    const float* Wa  = (const float*)d_in[10];
    const float* Ua  = (const float*)d_in[11];
    const float* ba  = (const float*)d_in[12];
    const float* Ww  = (const float*)d_in[13];
    const float* Uw  = (const float*)d_in[14];
    const float* bw  = (const float*)d_in[15];
    float* out = (float*)d_out;

    void *pXW, *pXWa, *pXwWw;
    cudaGetSymbolAddress(&pXW, g_XW);
    cudaGetSymbolAddress(&pXWa, g_XWa);
    cudaGetSymbolAddress(&pXwWw, g_XwWw);

    cudaFuncSetAttribute(lattice_seq_kernel,
                         cudaFuncAttributeMaxDynamicSharedMemorySize, SMEM_BYTES);

    detect_kernel<<<1, 256>>>((const unsigned*)wm);
    expand_masks<<<64, 256>>>(wm);
    gemm_bias_kernel<<<dim3(24, 64), 256>>>(x, nullptr, W, b, (float*)pXW, Tt, 128, H3);
    gemm_bias_kernel<<<dim3(8, 64), 256>>>(x, nullptr, Wa, ba, (float*)pXWa, Tt, 128, Hh);
    gemm_bias_kernel<<<dim3(24, 256), 256>>>(emb, wid, Ww, bw, (float*)pXwWw,
                                             Tt * 4, 256, H3);
    lattice_seq_kernel<<<NCTA, NTH, SMEM_BYTES>>>(h0, c0, wst, U, Ua, Uw, out);
}

// round 12
// speedup vs baseline: 1.8247x; 1.1813x over previous
#include <cuda_runtime.h>
#include <cstdint>

#define Tt   4096
#define Hh   512
#define H3   1536
#define NCTA 128
#define NTH  256

__device__ float g_XW  [Tt * H3];
__device__ float g_XWa [Tt * Hh];
__device__ float g_XwWw[Tt * 4 * H3];
__device__ float g_cw  [2][4 * Hh];
__device__ float g_hbuf[2][Hh];
__device__ int   g_maskw[Tt * 4];
__device__ unsigned g_flag_h [NCTA * 64];
__device__ unsigned g_flag_cw[NCTA * 64];
__device__ int g_mask_kind;

// ---- mask dtype detection (u8/i32/f32) ----
__global__ void detect_kernel(const unsigned* __restrict__ wm) {
    __shared__ int f_gt1, f_f32;
    if (threadIdx.x == 0) { f_gt1 = 0; f_f32 = 0; }
    __syncthreads();
    for (int i = threadIdx.x; i < 4096; i += blockDim.x) {
        unsigned v = wm[i];
        if (v == 0x3F800000u) atomicOr(&f_f32, 1);
        else if (v > 1u)      atomicOr(&f_gt1, 1);
    }
    __syncthreads();
    if (threadIdx.x == 0) g_mask_kind = f_f32 ? 2 : (f_gt1 ? 0 : 1);
}

// ---- expand masks to int32 + zero barrier flags ----
__global__ void expand_masks(const void* __restrict__ wm) {
    int i = blockIdx.x * blockDim.x + threadIdx.x;   // 0..16383
    int mk = g_mask_kind;
    int m;
    if (mk == 0)      m = ((const unsigned char*)wm)[i] != 0;
    else if (mk == 2) m = ((const float*)wm)[i] != 0.f;
    else              m = ((const int*)wm)[i] != 0;
    g_maskw[i] = m;
    if (i < NCTA * 64) { g_flag_h[i] = 0u; g_flag_cw[i] = 0u; }
}

// ---- merged batched GEMM: 3 segments dispatched on blockIdx.x ----
#define BM 64
#define BN 64
#define BK 8
__global__ void gemm_all_kernel(const float* __restrict__ x, const int* __restrict__ wid,
                                const float* __restrict__ emb,
                                const float* __restrict__ W,  const float* __restrict__ b,
                                const float* __restrict__ Wa, const float* __restrict__ ba,
                                const float* __restrict__ Ww, const float* __restrict__ bw) {
    __shared__ float As[BK][BM];
    __shared__ float Bs[BK][BN];
    int bx = blockIdx.x;
    const float* A; const int* idx = nullptr;
    const float* B; const float* bias; float* C;
    int K, N, nx, rel;
    if (bx < 1536)      { rel = bx;        A = x;   B = W;  bias = b;  C = g_XW;   K = 128; N = 1536; nx = 24; }
    else if (bx < 2048) { rel = bx - 1536; A = x;   B = Wa; bias = ba; C = g_XWa;  K = 128; N = 512;  nx = 8;  }
    else                { rel = bx - 2048; A = emb; B = Ww; bias = bw; C = g_XwWw; K = 256; N = 1536; nx = 24; idx = wid; }
    const int bn0 = (rel % nx) * BN, bm0 = (rel / nx) * BM;
    const int tid = threadIdx.x;
    const int tx = tid & 15, ty = tid >> 4;
    const int lm = tid >> 2, lkk = (tid & 3) * 2;
    int arow = bm0 + lm;
    if (idx) arow = idx[arow];
    const float* aptr = A + (size_t)arow * K;
    const int bn = tid & 63, bkk = tid >> 6;

    float acc[4][4];
#pragma unroll
    for (int i = 0; i < 4; ++i)
#pragma unroll
        for (int j = 0; j < 4; ++j) acc[i][j] = 0.f;

    for (int k0 = 0; k0 < K; k0 += BK) {
        As[lkk][lm]     = aptr[k0 + lkk];
        As[lkk + 1][lm] = aptr[k0 + lkk + 1];
        Bs[bkk][bn]     = B[(size_t)(k0 + bkk) * N + bn0 + bn];
        Bs[bkk + 4][bn] = B[(size_t)(k0 + bkk + 4) * N + bn0 + bn];
        __syncthreads();
#pragma unroll
        for (int kk = 0; kk < BK; ++kk) {
            float4 av = *reinterpret_cast<const float4*>(&As[kk][ty * 4]);
            float4 bv = *reinterpret_cast<const float4*>(&Bs[kk][tx * 4]);
            float a[4] = {av.x, av.y, av.z, av.w};
            float b4[4] = {bv.x, bv.y, bv.z, bv.w};
#pragma unroll
            for (int i = 0; i < 4; ++i)
#pragma unroll
                for (int j = 0; j < 4; ++j) acc[i][j] += a[i] * b4[j];
        }
        __syncthreads();
    }
#pragma unroll
    for (int i = 0; i < 4; ++i) {
        size_t rbase = (size_t)(bm0 + ty * 4 + i) * N + bn0 + tx * 4;
#pragma unroll
        for (int j = 0; j < 4; ++j)
            C[rbase + j] = acc[i][j] + bias[bn0 + tx * 4 + j];
    }
}

// ---- contention-free flag barrier primitives ----
__device__ __forceinline__ void flag_post(unsigned* slot, unsigned epoch) {
    asm volatile("st.release.gpu.u32 [%0], %1;" :: "l"(slot), "r"(epoch) : "memory");
}
__device__ __forceinline__ void flag_wait(const unsigned* slot, unsigned epoch) {
    unsigned v;
    do {
        asm volatile("ld.acquire.gpu.u32 %0, [%1];" : "=r"(v) : "l"(slot) : "memory");
    } while (v < epoch);
}

// ---- cp.async helpers ----
__device__ __forceinline__ void cp16(uint32_t saddr, const void* g) {
    asm volatile("cp.async.cg.shared.global [%0], [%1], 16;" :: "r"(saddr), "l"(g) : "memory");
}
__device__ __forceinline__ void cp_commit() {
    asm volatile("cp.async.commit_group;" ::: "memory");
}
__device__ __forceinline__ void cp_wait0() {
    asm volatile("cp.async.wait_group 0;" ::: "memory");
}

struct CBuf {           // 288 B, 16B-aligned fields
    float xw[12];       // XW cols   (g*4+jl)
    float xa[4];        // XWa cols
    float xww[48];      // XwWw cols (w*12 + g*4 + jl)
    int   mask[4];
    int   start[4];
};

__device__ __forceinline__ float sigf(float v) { return 1.f / (1.f + expf(-v)); }

#define SMEM_FLOATS 6144
#define SMEM_BYTES  (SMEM_FLOATS * 4)

__global__ void __launch_bounds__(NTH, 1)
lattice_seq_kernel(const float* __restrict__ h0, const float* __restrict__ c0,
                   const int* __restrict__ wstarts,
                   const float* __restrict__ U, const float* __restrict__ Ua,
                   const float* __restrict__ Uw, float* __restrict__ out) {
    extern __shared__ float sm[];
    float4* sh4    = (float4*)sm;            // h_prev  [512]f
    float4* scw4   = (float4*)(sm + 512);    // c_w     [2048]f
    float*  sg     = sm + 2560;              // 12 gates
    float*  salpha = sm + 2576;              // 16
    float*  rc     = sm + 2592;              // ring: own c slice [6][4]
    float*  rhuw   = sm + 2620;              // ring: own huw cols [6][12]
    CBuf*   cbuf   = (CBuf*)(sm + 2704);     // triple buffer (16B aligned)

    const int tid = threadIdx.x;
    const int r   = blockIdx.x;
    const int d   = tid >> 3,  l   = tid & 7;
    const int g16 = tid >> 4,  l16 = tid & 15;
    const int ajl = g16 & 3,   aw  = g16 >> 2;

    // ========== init: weights -> registers via coalesced SMEM staging ==========
    float wreg[64];   // U col slice (d<12) or Uw col slice (12<=d<24)
    float ua[32];     // Ua col slice
    {
        for (int e = tid; e < 3 * 512; e += NTH) {
            int gg = e >> 9, i = e & 511;
            float4 v = *reinterpret_cast<const float4*>(&U[(size_t)i * H3 + gg * 512 + r * 4]);
            sm[(gg * 4 + 0) * 512 + i] = v.x; sm[(gg * 4 + 1) * 512 + i] = v.y;
            sm[(gg * 4 + 2) * 512 + i] = v.z; sm[(gg * 4 + 3) * 512 + i] = v.w;
        }
        __syncthreads();
        if (d < 12) {
            int base = d * 512 + l * 4;
#pragma unroll
            for (int m = 0; m < 16; ++m)
#pragma unroll
                for (int k = 0; k < 4; ++k) wreg[m * 4 + k] = sm[base + m * 32 + k];
        }
        __syncthreads();
        for (int e = tid; e < 3 * 512; e += NTH) {
            int gg = e >> 9, i = e & 511;
            float4 v = *reinterpret_cast<const float4*>(&Uw[(size_t)i * H3 + gg * 512 + r * 4]);
            sm[(gg * 4 + 0) * 512 + i] = v.x; sm[(gg * 4 + 1) * 512 + i] = v.y;
            sm[(gg * 4 + 2) * 512 + i] = v.z; sm[(gg * 4 + 3) * 512 + i] = v.w;
        }
        __syncthreads();
        if (d >= 12 && d < 24) {
            int base = (d - 12) * 512 + l * 4;
#pragma unroll
            for (int m = 0; m < 16; ++m)
#pragma unroll
                for (int k = 0; k < 4; ++k) wreg[m * 4 + k] = sm[base + m * 32 + k];
        }
        __syncthreads();
        for (int e = tid; e < 512; e += NTH) {
            float4 v = *reinterpret_cast<const float4*>(&Ua[(size_t)e * Hh + r * 4]);
            sm[0 * 512 + e] = v.x; sm[1 * 512 + e] = v.y;
            sm[2 * 512 + e] = v.z; sm[3 * 512 + e] = v.w;
        }
        __syncthreads();
        {
            int base = ajl * 512 + l16 * 4;
#pragma unroll
            for (int m = 0; m < 8; ++m)
#pragma unroll
                for (int k = 0; k < 4; ++k) ua[m * 4 + k] = sm[base + m * 64 + k];
        }
        __syncthreads();
    }

    // cp.async prefetch of step t1 constants into cbuf[t1%3] (threads 160..177)
    auto issue_prefetch = [&](int t1) {
        CBuf* nb = cbuf + (t1 % 3);
        int e = tid - 160;
        if (e >= 0 && e < 18) {
            const void* src;
            uint32_t dst;
            if (e < 12) {
                int w = e / 3, gg = e % 3;
                src = &g_XwWw[((size_t)(t1 * 4 + w)) * H3 + gg * 512 + r * 4];
                dst = (uint32_t)__cvta_generic_to_shared(&nb->xww[e * 4]);
            } else if (e < 15) {
                int gg = e - 12;
                src = &g_XW[(size_t)t1 * H3 + gg * 512 + r * 4];
                dst = (uint32_t)__cvta_generic_to_shared(&nb->xw[gg * 4]);
            } else if (e == 15) {
                src = &g_XWa[(size_t)t1 * Hh + r * 4];
                dst = (uint32_t)__cvta_generic_to_shared(nb->xa);
            } else if (e == 16) {
                src = &wstarts[t1 * 4];
                dst = (uint32_t)__cvta_generic_to_shared(nb->start);
            } else {
                src = &g_maskw[t1 * 4];
                dst = (uint32_t)__cvta_generic_to_shared(nb->mask);
            }
            cp16(dst, src);
        }
        if (tid >= 160 && tid < 192) cp_commit();
    };

    // prime step 0 and step 1 constants
    issue_prefetch(0);
    issue_prefetch(1);
    if (tid >= 160 && tid < 192) cp_wait0();
    __syncthreads();

    unsigned lt = 0;   // late-step epoch (identical across CTAs)

    for (int t = 0; t < Tt; ++t) {
        CBuf* cb = cbuf + (t % 3);
        CBuf* nb = cbuf + ((t + 1) % 3);

        const int m0 = cb->mask[0], m1 = cb->mask[1], m2 = cb->mask[2], m3 = cb->mask[3];
        const int anyw = m0 | m1 | m2 | m3;
        const int haslate = (m0 & (cb->start[0] == t - 1)) | (m1 & (cb->start[1] == t - 1))
                          | (m2 & (cb->start[2] == t - 1)) | (m3 & (cb->start[3] == t - 1));
        if (haslate) ++lt;

        // ---- per-slice pipelined h poll + stage (flag i guards slice i) ----
        if (tid < 128) {
            if (t == 0) sh4[tid] = ((const float4*)h0)[tid];
            else {
                flag_wait(&g_flag_h[tid * 64], (unsigned)t);
                sh4[tid] = __ldcg((const float4*)g_hbuf[(t - 1) & 1] + tid);
            }
        }
        __syncthreads();   // S1 (also orders prior step's combine before cp.async reuse)

        // warp5: drain pending cp.async groups, then issue step t+2
        if (tid >= 160 && tid < 192) cp_wait0();
        if (t + 2 < Tt) issue_prefetch(t + 2);

        // ---- 24 dots from registers (tid<192); scw prestage (tid>=192, no-late) ----
        if (tid < 192) {
            float a0 = 0.f, a1 = 0.f, a2 = 0.f, a3 = 0.f;
#pragma unroll
            for (int m = 0; m < 16; ++m) {
                float4 hv = sh4[m * 8 + l];
                a0 += wreg[m * 4 + 0] * hv.x;
                a1 += wreg[m * 4 + 1] * hv.y;
                a2 += wreg[m * 4 + 2] * hv.z;
                a3 += wreg[m * 4 + 3] * hv.w;
            }
            float acc = (a0 + a1) + (a2 + a3);
            acc += __shfl_down_sync(0xffffffffu, acc, 4, 8);
            acc += __shfl_down_sync(0xffffffffu, acc, 2, 8);
            acc += __shfl_down_sync(0xffffffffu, acc, 1, 8);
            if (l == 0) {
                if (d < 12) sg[d] = cb->xw[d] + acc;
                else if (t > 0) rhuw[((t - 1) % 6) * 12 + (d - 12)] = acc;
            }
        } else if (anyw && !haslate) {
            const float4* src = (const float4*)g_cw[t & 1];
            for (int e = tid - 192; e < 512; e += 64)
                scw4[e] = __ldcg(src + e);
        }
        __syncthreads();   // S2

        // ---- word phase ----
        if (haslate) {
            if (tid < 32) {
                if (tid < 16) {          // late words of step t (start == t-1)
                    int w = tid >> 2, jl = tid & 3;
                    if (cb->mask[w] && cb->start[w] == t - 1) {
                        int s = cb->start[w], slot = (s % 6) * 12;
                        float fv = cb->xww[w * 12 + 0 + jl] + rhuw[slot + 0 + jl];
                        float iv = cb->xww[w * 12 + 4 + jl] + rhuw[slot + 4 + jl];
                        float gv = cb->xww[w * 12 + 8 + jl] + rhuw[slot + 8 + jl];
                        float cs = rc[(s % 6) * 4 + jl];
                        g_cw[t & 1][(w << 9) + r * 4 + jl] = sigf(fv) * cs + sigf(iv) * tanhf(gv);
                    }
                } else if (t + 1 < Tt) { // early words of step t+1 (start <= t-1)
                    int w = (tid - 16) >> 2, jl = tid & 3;
                    if (nb->mask[w] && nb->start[w] != t) {
                        int s = nb->start[w], slot = (s % 6) * 12;
                        float fv = nb->xww[w * 12 + 0 + jl] + rhuw[slot + 0 + jl];
                        float iv = nb->xww[w * 12 + 4 + jl] + rhuw[slot + 4 + jl];
                        float gv = nb->xww[w * 12 + 8 + jl] + rhuw[slot + 8 + jl];
                        float cs = rc[(s % 6) * 4 + jl];
                        g_cw[(t + 1) & 1][(w << 9) + r * 4 + jl] = sigf(fv) * cs + sigf(iv) * tanhf(gv);
                    }
                }
                __syncwarp();
                if (tid == 0) flag_post(&g_flag_cw[r * 64], lt);
            }
            // per-slice pipelined c_w fetch: flag i guards CTA i's 4 slices
            if (tid < 128) {
                flag_wait(&g_flag_cw[tid * 64], lt);
                const float4* src = (const float4*)g_cw[t & 1];
#pragma unroll
                for (int w = 0; w < 4; ++w)
                    scw4[(w << 7) + tid] = __ldcg(src + (w << 7) + tid);
            }
        } else if (tid >= 16 && tid < 32 && t + 1 < Tt) {   // early words of step t+1
            int w = (tid - 16) >> 2, jl = tid & 3;
            if (nb->mask[w] && nb->start[w] != t) {
                int s = nb->start[w], slot = (s % 6) * 12;
                float fv = nb->xww[w * 12 + 0 + jl] + rhuw[slot + 0 + jl];
                float iv = nb->xww[w * 12 + 4 + jl] + rhuw[slot + 4 + jl];
                float gv = nb->xww[w * 12 + 8 + jl] + rhuw[slot + 8 + jl];
                float cs = rc[(s % 6) * 4 + jl];
                g_cw[(t + 1) & 1][(w << 9) + r * 4 + jl] = sigf(fv) * cs + sigf(iv) * tanhf(gv);
            }
        }
        // gate activations (threads 128-139; run concurrent with cw exchange)
        if (tid >= 128 && tid < 140) {
            int dd = tid - 128;
            float v = sg[dd];
            sg[dd] = (dd >= 8) ? tanhf(v) : sigf(v);
        }
        __syncthreads();   // S3

        // ---- 16 alpha dots (c_w[w] @ Ua col) from registers ----
        if (anyw) {
            float a0 = 0.f, a1 = 0.f, a2 = 0.f, a3 = 0.f;
            const float4* cc4 = scw4 + (aw << 7);
#pragma unroll
            for (int m = 0; m < 8; ++m) {
                float4 cv = cc4[m * 16 + l16];
                a0 += ua[m * 4 + 0] * cv.x;
                a1 += ua[m * 4 + 1] * cv.y;
                a2 += ua[m * 4 + 2] * cv.z;
                a3 += ua[m * 4 + 3] * cv.w;
            }
            float acc = (a0 + a1) + (a2 + a3);
            acc += __shfl_down_sync(0xffffffffu, acc, 8, 16);
            acc += __shfl_down_sync(0xffffffffu, acc, 4, 16);
            acc += __shfl_down_sync(0xffffffffu, acc, 2, 16);
            acc += __shfl_down_sync(0xffffffffu, acc, 1, 16);
            if (l16 == 0) salpha[g16] = sigf(cb->xa[ajl] + acc);
            __syncthreads();   // S4
        }

        // ---- combine in warp 0; lane 0 publishes h slice + flag immediately ----
        if (tid < 32) {
            float h1 = 0.f, c1 = 0.f;
            if (tid < 4) {
                int j = r * 4 + tid;
                float ig = sg[tid], og = sg[4 + tid], gg = sg[8 + tid];
                if (anyw) {
                    float e0 = expf(ig);
                    float den = e0, num = e0 * gg;
#pragma unroll
                    for (int w = 0; w < 4; ++w)
                        if (cb->mask[w]) {
                            float ew = expf(salpha[(w << 2) + tid]);
                            den += ew;
                            num += ew * ((const float*)scw4)[(w << 9) + j];
                        }
                    c1 = num / den;
                } else {
                    float cprev = (t == 0) ? c0[j] : rc[((t - 1) % 6) * 4 + tid];
                    c1 = (1.f - ig) * cprev + ig * gg;
                }
                h1 = og * tanhf(c1);
                rc[(t % 6) * 4 + tid] = c1;
            }
            float x0 = __shfl_sync(0xffffffffu, h1, 0);
            float x1 = __shfl_sync(0xffffffffu, h1, 1);
            float x2 = __shfl_sync(0xffffffffu, h1, 2);
            float x3 = __shfl_sync(0xffffffffu, h1, 3);
            if (tid == 0) {
                float4 hv; hv.x = x0; hv.y = x1; hv.z = x2; hv.w = x3;
                ((float4*)g_hbuf[t & 1])[r] = hv;
                flag_post(&g_flag_h[r * 64], (unsigned)(t + 1));
            }
            if (tid < 4) {                     // output writes, off critical path
                out[(size_t)t * 1024 + r * 4 + tid]       = h1;
                out[(size_t)t * 1024 + 512 + r * 4 + tid] = c1;
            }
        }
        // no end-of-step sync: S1 of the next step orders all reuse
    }
}

extern "C" void kernel_launch(void* const* d_in, const int* in_sizes, int n_in,
                              void* d_out, int out_size) {
    const float* x   = (const float*)d_in[0];
    const int*   wid = (const int*)d_in[1];
    const int*   wst = (const int*)d_in[2];
    const void*  wm  = d_in[3];
    const float* h0  = (const float*)d_in[4];
    const float* c0  = (const float*)d_in[5];
    const float* emb = (const float*)d_in[6];
    const float* W   = (const float*)d_in[7];
    const float* U   = (const float*)d_in[8];
    const float* b   = (const float*)d_in[9];
    const float* Wa  = (const float*)d_in[10];
    const float* Ua  = (const float*)d_in[11];
    const float* ba  = (const float*)d_in[12];
    const float* Ww  = (const float*)d_in[13];
    const float* Uw  = (const float*)d_in[14];
    const float* bw  = (const float*)d_in[15];
    float* out = (float*)d_out;

    cudaFuncSetAttribute(lattice_seq_kernel,
                         cudaFuncAttributeMaxDynamicSharedMemorySize, SMEM_BYTES);

    detect_kernel<<<1, 256>>>((const unsigned*)wm);
    expand_masks<<<64, 256>>>(wm);
    gemm_all_kernel<<<8192, 256>>>(x, wid, emb, W, b, Wa, ba, Ww, bw);
    lattice_seq_kernel<<<NCTA, NTH, SMEM_BYTES>>>(h0, c0, wst, U, Ua, Uw, out);
}